// round 10
// baseline (speedup 1.0000x reference)
#include <cuda_runtime.h>
#include <cuda_fp16.h>
#include <cstdint>

#define B_ 2048
#define N_ 64
#define D_ 256
#define MT 128
#define NTH 512
#define STEPS 4

// ---------------------------------------------------------------------------
// w image (fp16, masked), slab-major: [n][slab16(16)][row(256)][16k*fp16=32B]
// ---------------------------------------------------------------------------
__device__ uint32_t g_w[(size_t)N_ * 16 * D_ * 8];   // 8 MB
__device__ float    g_bias[N_ * D_];
__device__ int      g_nact[N_];

__device__ __forceinline__ void split2h(float a, float b, uint32_t& hi, uint32_t& lo) {
    __half2 H = __floats2half2_rn(a, b);
    float ra = a - __half2float(H.x);
    float rb = b - __half2float(H.y);
    __half2 L = __floats2half2_rn(ra, rb);
    hi = *reinterpret_cast<uint32_t*>(&H);
    lo = *reinterpret_cast<uint32_t*>(&L);
}

__device__ __forceinline__ uint32_t smem_u32(const void* p) {
    uint32_t a;
    asm("{ .reg .u64 t; cvta.to.shared.u64 t, %1; cvt.u32.u64 %0, t; }"
        : "=r"(a) : "l"(p));
    return a;
}

__device__ __forceinline__ void cp16(uint32_t dst, const void* src) {
    asm volatile("cp.async.ca.shared.global [%0], [%1], 16;"
                 :: "r"(dst), "l"(src) : "memory");
}

#define LDSM4(r, addr) \
    asm volatile("ldmatrix.sync.aligned.m8n8.x4.shared.b16 {%0,%1,%2,%3}, [%4];" \
        : "=r"((r)[0]), "=r"((r)[1]), "=r"((r)[2]), "=r"((r)[3]) : "r"(addr))

#define MMA16816(d, a, b0, b1) \
    asm volatile("mma.sync.aligned.m16n8k16.row.col.f32.f16.f16.f32 " \
        "{%0,%1,%2,%3}, {%4,%5,%6,%7}, {%8,%9}, {%0,%1,%2,%3};" \
        : "+f"((d)[0]), "+f"((d)[1]), "+f"((d)[2]), "+f"((d)[3]) \
        : "r"((a)[0]), "r"((a)[1]), "r"((a)[2]), "r"((a)[3]), "r"(b0), "r"(b1))

// ---------------------------------------------------------------------------
// Fused prep: masked fp16 w image; block.y==0 also does bias + nact.
// ---------------------------------------------------------------------------
__global__ void prep_kernel(const float* __restrict__ w,
                            const float* __restrict__ wm,
                            const float* __restrict__ b,
                            const float* __restrict__ bm) {
    int n = blockIdx.x;
    int t = threadIdx.x;
    int j = blockIdx.y * 16 + (t >> 4);
    int c = t & 15;
    const float4* wp = (const float4*)(w  + ((size_t)n * D_ + j) * D_) + c * 4;
    const float4* mp = (const float4*)(wm + ((size_t)n * D_ + j) * D_) + c * 4;
    uint32_t* o = g_w + (((size_t)n * 16 + c) * D_ + j) * 8;
#pragma unroll
    for (int i4 = 0; i4 < 4; i4++) {
        float4 a = wp[i4];
        float4 m = mp[i4];
        __half2 h0 = __floats2half2_rn(a.x * m.x, a.y * m.y);
        __half2 h1 = __floats2half2_rn(a.z * m.z, a.w * m.w);
        o[i4 * 2]     = *reinterpret_cast<uint32_t*>(&h0);
        o[i4 * 2 + 1] = *reinterpret_cast<uint32_t*>(&h1);
    }
    if (blockIdx.y == 0) {
        __shared__ int cnt;
        if (t == 0) cnt = 0;
        __syncthreads();
        float m = bm[n * D_ + t];
        g_bias[n * D_ + t] = b[n * D_ + t] * m;
        unsigned ballot = __ballot_sync(0xFFFFFFFFu, m != 0.0f);
        if ((t & 31) == 0) atomicAdd(&cnt, __popc(ballot));
        __syncthreads();
        if (t == 0) g_nact[n] = cnt;
    }
}

// ---------------------------------------------------------------------------
// smem layout (1 CTA/SM, 165KB):
//   XH [128][528B], XL [128][528B], W [2 buf][2 k16][256 rows * 32B], bias
// ---------------------------------------------------------------------------
#define XSTR    528
#define OFF_XH  0u
#define OFF_XL  67584u
#define OFF_W   135168u
#define WBUF    16384u
#define WSUB    8192u
#define OFF_BS  167936u
#define SMEM_SZ 168960

template<int NACT>
__device__ __forceinline__ void run_main(
    char* smem, const char* gw, bool ldr, uint32_t wdst,
    uint32_t c0, uint32_t c1, uint32_t aBaseH, uint32_t aBaseL,
    uint32_t bBase, int warp_m, int warp_n, int l)
{
    constexpr int NSLAB = NACT >> 5;
    const int tc = l & 3;

    // bias cache (step-invariant)
    const float* bsp = (const float*)(smem + OFF_BS);
    float bias_r[4][2][2];
#pragma unroll
    for (int p = 0; p < 4; p++) {
        if (NACT == 256 || p * 64 + warp_n * 16 < NACT) {
#pragma unroll
            for (int hn = 0; hn < 2; hn++) {
                int j = p * 64 + warp_n * 16 + hn * 8 + tc * 2;
                bias_r[p][hn][0] = bsp[j];
                bias_r[p][hn][1] = bsp[j + 1];
            }
        }
    }

    float acc[2][8][4];
    uint32_t buf = 0;

    for (int step = 0; step < STEPS; step++) {
#pragma unroll
        for (int i = 0; i < 2; i++)
#pragma unroll
            for (int jn = 0; jn < 8; jn++)
#pragma unroll
                for (int r = 0; r < 4; r++) acc[i][jn][r] = 0.0f;

#pragma unroll
        for (int s = 0; s < NSLAB; s++) {
            bool last = (step == STEPS - 1) && (s == NSLAB - 1);
            if (!last && ldr) {
                int sn = (s + 1 == NSLAB) ? 0 : s + 1;
                const char* src = gw + (size_t)sn * 16384;
                uint32_t d = wdst + (buf ^ 1u) * WBUF;
                cp16(d + c0, src);
                cp16(d + c1, src + 16);
                cp16(d + WSUB + c0, src + 8192);
                cp16(d + WSUB + c1, src + 8192 + 16);
            }
            asm volatile("cp.async.commit_group;" ::: "memory");

            const uint32_t wOff = buf * WBUF;
#pragma unroll
            for (int kk = 0; kk < 2; kk++) {
                const uint32_t aoff = (uint32_t)(s * 64 + kk * 32);
                uint32_t aH0[4], aH1[4], aL0[4], aL1[4];
                LDSM4(aH0, aBaseH + aoff);
                LDSM4(aH1, aBaseH + 8448 + aoff);   // +16 rows * 528
                LDSM4(aL0, aBaseL + aoff);
                LDSM4(aL1, aBaseL + 8448 + aoff);
                const uint32_t kOff = wOff + (uint32_t)kk * WSUB;
#pragma unroll
                for (int p = 0; p < 4; p++) {
                    if (NACT == 256 || p * 64 + warp_n * 16 < NACT) {
                        uint32_t bW[4];
                        LDSM4(bW, bBase + kOff + (uint32_t)(p * 64 + warp_n * 16) * 32);
                        MMA16816(acc[0][2 * p],     aH0, bW[0], bW[1]);
                        MMA16816(acc[0][2 * p + 1], aH0, bW[2], bW[3]);
                        MMA16816(acc[1][2 * p],     aH1, bW[0], bW[1]);
                        MMA16816(acc[1][2 * p + 1], aH1, bW[2], bW[3]);
                        MMA16816(acc[0][2 * p],     aL0, bW[0], bW[1]);
                        MMA16816(acc[0][2 * p + 1], aL0, bW[2], bW[3]);
                        MMA16816(acc[1][2 * p],     aL1, bW[0], bW[1]);
                        MMA16816(acc[1][2 * p + 1], aL1, bW[2], bW[3]);
                    }
                }
            }

            if (s < NSLAB - 1) {
                asm volatile("cp.async.wait_group 0;" ::: "memory");
                __syncthreads();
            }
            buf ^= 1u;
        }

        // ---- epilogue: x += relu(acc + b), re-split fp16 ----
        __syncthreads();
        int q4 = l >> 2;
#pragma unroll
        for (int mt = 0; mt < 2; mt++) {
            int mrow = warp_m * 32 + mt * 16 + q4;
#pragma unroll
            for (int p = 0; p < 4; p++) {
                if (!(NACT == 256 || p * 64 + warp_n * 16 < NACT)) continue;
#pragma unroll
                for (int hn = 0; hn < 2; hn++) {
                    int j = p * 64 + warp_n * 16 + hn * 8 + tc * 2;
                    float b0 = bias_r[p][hn][0], b1 = bias_r[p][hn][1];
                    float* a4 = acc[mt][2 * p + hn];
#pragma unroll
                    for (int half = 0; half < 2; half++) {
                        int m = mrow + half * 8;
                        uint32_t off = (uint32_t)m * XSTR + (uint32_t)j * 2;
                        uint32_t h  = *(uint32_t*)(smem + OFF_XH + off);
                        uint32_t lo = *(uint32_t*)(smem + OFF_XL + off);
                        __half2 H = *(__half2*)&h;
                        __half2 L = *(__half2*)&lo;
                        float x0 = __half2float(H.x) + __half2float(L.x)
                                   + fmaxf(a4[half * 2]     + b0, 0.0f);
                        float x1 = __half2float(H.y) + __half2float(L.y)
                                   + fmaxf(a4[half * 2 + 1] + b1, 0.0f);
                        uint32_t nh, nl;
                        split2h(x0, x1, nh, nl);
                        *(uint32_t*)(smem + OFF_XH + off) = nh;
                        *(uint32_t*)(smem + OFF_XL + off) = nl;
                    }
                }
            }
        }
        asm volatile("cp.async.wait_group 0;" ::: "memory");
        __syncthreads();
    }
}

__global__ __launch_bounds__(NTH, 1)
void recur_kernel(const float* __restrict__ x_in, float* __restrict__ out) {
    extern __shared__ char smem[];
    uint32_t sb = smem_u32(smem);
    int n  = blockIdx.y;
    int m0 = blockIdx.x * MT;
    int t  = threadIdx.x;
    int l  = t & 31;
    int wid = t >> 5;
    int warp_m = wid >> 2;   // 0..3
    int warp_n = wid & 3;    // 0..3

    int nact = g_nact[n];
    if (t < D_) ((float*)(smem + OFF_BS))[t] = g_bias[n * D_ + t];

    // ---- initial x load + fp16 split (512 threads, 128 rows) ----
    {
        int m = t >> 2, q = t & 3;
        const float4* src =
            (const float4*)(x_in + ((size_t)(m0 + m) * N_ + n) * D_) + q * 16;
        char* rowH = smem + OFF_XH + m * XSTR;
        char* rowL = smem + OFF_XL + m * XSTR;
#pragma unroll
        for (int c = 0; c < 16; c++) {
            float4 v = src[c];
            int k = q * 64 + c * 4;
            uint32_t h0, l0, h1, l1;
            split2h(v.x, v.y, h0, l0);
            split2h(v.z, v.w, h1, l1);
            *(uint32_t*)(rowH + k * 2)     = h0;
            *(uint32_t*)(rowL + k * 2)     = l0;
            *(uint32_t*)(rowH + k * 2 + 4) = h1;
            *(uint32_t*)(rowL + k * 2 + 4) = l1;
        }
    }

    const bool ldr = (t < nact);
    const char* gw = (const char*)g_w + ((size_t)n * 16 * D_ + t) * 32;
    const uint32_t swz = ((uint32_t)(t >> 2) & 1u) * 16u;
    const uint32_t c0 = swz, c1 = 16u - swz;
    const uint32_t wdst = sb + OFF_W + (uint32_t)t * 32;

    // preload slab 0 -> buf 0
    if (ldr) {
        cp16(wdst + c0, gw);
        cp16(wdst + c1, gw + 16);
        cp16(wdst + WSUB + c0, gw + 8192);
        cp16(wdst + WSUB + c1, gw + 8192 + 16);
    }
    asm volatile("cp.async.commit_group;" ::: "memory");
    asm volatile("cp.async.wait_group 0;" ::: "memory");
    __syncthreads();

    const uint32_t aBaseH = sb + OFF_XH + (uint32_t)(warp_m * 32 + (l & 15)) * XSTR
                            + (uint32_t)(l >> 4) * 16;
    const uint32_t aBaseL = aBaseH + (OFF_XL - OFF_XH);
    const int br = (l & 7) + ((l >> 4) & 1) * 8;
    const int bh = (l >> 3) & 1;
    const uint32_t bBase = sb + OFF_W + (uint32_t)br * 32
                           + (uint32_t)((bh ^ ((br >> 2) & 1)) * 16);

    switch (nact) {
        case 128: run_main<128>(smem, gw, ldr, wdst, c0, c1, aBaseH, aBaseL, bBase, warp_m, warp_n, l); break;
        case 160: run_main<160>(smem, gw, ldr, wdst, c0, c1, aBaseH, aBaseL, bBase, warp_m, warp_n, l); break;
        case 192: run_main<192>(smem, gw, ldr, wdst, c0, c1, aBaseH, aBaseL, bBase, warp_m, warp_n, l); break;
        case 224: run_main<224>(smem, gw, ldr, wdst, c0, c1, aBaseH, aBaseL, bBase, warp_m, warp_n, l); break;
        default:  run_main<256>(smem, gw, ldr, wdst, c0, c1, aBaseH, aBaseL, bBase, warp_m, warp_n, l); break;
    }

    // ---- final store: x = hi + lo ----
    {
        int m = t >> 2, q = t & 3;
        float4* dst = (float4*)(out + ((size_t)(m0 + m) * N_ + n) * D_) + q * 16;
        const char* rowH = smem + OFF_XH + m * XSTR;
        const char* rowL = smem + OFF_XL + m * XSTR;
#pragma unroll
        for (int c = 0; c < 16; c++) {
            int k = q * 64 + c * 4;
            uint32_t h0  = *(const uint32_t*)(rowH + k * 2);
            uint32_t l0  = *(const uint32_t*)(rowL + k * 2);
            uint32_t h1  = *(const uint32_t*)(rowH + k * 2 + 4);
            uint32_t l1  = *(const uint32_t*)(rowL + k * 2 + 4);
            __half2 H0 = *(__half2*)&h0, L0 = *(__half2*)&l0;
            __half2 H1 = *(__half2*)&h1, L1 = *(__half2*)&l1;
            float4 v;
            v.x = __half2float(H0.x) + __half2float(L0.x);
            v.y = __half2float(H0.y) + __half2float(L0.y);
            v.z = __half2float(H1.x) + __half2float(L1.x);
            v.w = __half2float(H1.y) + __half2float(L1.y);
            dst[c] = v;
        }
    }
}

// ---------------------------------------------------------------------------
extern "C" void kernel_launch(void* const* d_in, const int* in_sizes, int n_in,
                              void* d_out, int out_size) {
    const float* x  = (const float*)d_in[0];
    const float* w  = (const float*)d_in[1];
    const float* b  = (const float*)d_in[2];
    const float* wm = (const float*)d_in[3];
    const float* bm = (const float*)d_in[4];
    float* out = (float*)d_out;

    prep_kernel<<<dim3(N_, 16), 256>>>(w, wm, b, bm);

    cudaFuncSetAttribute(recur_kernel,
                         cudaFuncAttributeMaxDynamicSharedMemorySize, SMEM_SZ);
    recur_kernel<<<dim3(B_ / MT, N_), NTH, SMEM_SZ>>>(x, out);
}

// round 11
// speedup vs baseline: 1.1925x; 1.1925x over previous
#include <cuda_runtime.h>
#include <cuda_fp16.h>
#include <cstdint>

#define B_ 2048
#define N_ 64
#define D_ 256
#define MT 64
#define NTH 256
#define STEPS 4

// ---------------------------------------------------------------------------
// w image (fp16, masked), slab-major: [n][slab16(16)][row(256)][16k*fp16=32B]
// ---------------------------------------------------------------------------
__device__ uint32_t g_w[(size_t)N_ * 16 * D_ * 8];   // 8 MB
__device__ float    g_bias[N_ * D_];
__device__ int      g_nact[N_];

__device__ __forceinline__ void split2h(float a, float b, uint32_t& hi, uint32_t& lo) {
    __half2 H = __floats2half2_rn(a, b);
    float ra = a - __half2float(H.x);
    float rb = b - __half2float(H.y);
    __half2 L = __floats2half2_rn(ra, rb);
    hi = *reinterpret_cast<uint32_t*>(&H);
    lo = *reinterpret_cast<uint32_t*>(&L);
}

__device__ __forceinline__ uint32_t smem_u32(const void* p) {
    uint32_t a;
    asm("{ .reg .u64 t; cvta.to.shared.u64 t, %1; cvt.u32.u64 %0, t; }"
        : "=r"(a) : "l"(p));
    return a;
}

__device__ __forceinline__ void cp16(uint32_t dst, const void* src) {
    asm volatile("cp.async.ca.shared.global [%0], [%1], 16;"
                 :: "r"(dst), "l"(src) : "memory");
}

#define LDSM4(r, addr) \
    asm volatile("ldmatrix.sync.aligned.m8n8.x4.shared.b16 {%0,%1,%2,%3}, [%4];" \
        : "=r"((r)[0]), "=r"((r)[1]), "=r"((r)[2]), "=r"((r)[3]) : "r"(addr))

#define MMA16816(d, a, b0, b1) \
    asm volatile("mma.sync.aligned.m16n8k16.row.col.f32.f16.f16.f32 " \
        "{%0,%1,%2,%3}, {%4,%5,%6,%7}, {%8,%9}, {%0,%1,%2,%3};" \
        : "+f"((d)[0]), "+f"((d)[1]), "+f"((d)[2]), "+f"((d)[3]) \
        : "r"((a)[0]), "r"((a)[1]), "r"((a)[2]), "r"((a)[3]), "r"(b0), "r"(b1))

// ---------------------------------------------------------------------------
// Fused prep: masked fp16 w image; block.y==0 also does bias + nact.
// ---------------------------------------------------------------------------
__global__ void prep_kernel(const float* __restrict__ w,
                            const float* __restrict__ wm,
                            const float* __restrict__ b,
                            const float* __restrict__ bm) {
    int n = blockIdx.x;
    int t = threadIdx.x;
    int j = blockIdx.y * 16 + (t >> 4);
    int c = t & 15;
    const float4* wp = (const float4*)(w  + ((size_t)n * D_ + j) * D_) + c * 4;
    const float4* mp = (const float4*)(wm + ((size_t)n * D_ + j) * D_) + c * 4;
    uint32_t* o = g_w + (((size_t)n * 16 + c) * D_ + j) * 8;
#pragma unroll
    for (int i4 = 0; i4 < 4; i4++) {
        float4 a = wp[i4];
        float4 m = mp[i4];
        __half2 h0 = __floats2half2_rn(a.x * m.x, a.y * m.y);
        __half2 h1 = __floats2half2_rn(a.z * m.z, a.w * m.w);
        o[i4 * 2]     = *reinterpret_cast<uint32_t*>(&h0);
        o[i4 * 2 + 1] = *reinterpret_cast<uint32_t*>(&h1);
    }
    if (blockIdx.y == 0) {
        __shared__ int cnt;
        if (t == 0) cnt = 0;
        __syncthreads();
        float m = bm[n * D_ + t];
        g_bias[n * D_ + t] = b[n * D_ + t] * m;
        unsigned ballot = __ballot_sync(0xFFFFFFFFu, m != 0.0f);
        if ((t & 31) == 0) atomicAdd(&cnt, __popc(ballot));
        __syncthreads();
        if (t == 0) g_nact[n] = cnt;
    }
}

// ---------------------------------------------------------------------------
// MT=64, occ 2 (R9 shape — empirically best). x carried as exact fp16 (hi,lo)
// pair; ONLY xh feeds the MMA (1-term). w error 2^-12 + x error 2^-12
// compound in quadrature: rel_err ~= 2.3e-4, under the 1e-3 gate.
// ---------------------------------------------------------------------------
#define XSTR    528
#define OFF_XH  0u
#define OFF_XL  33792u
#define OFF_W   67584u
#define WBUF    16384u
#define WSUB    8192u
#define OFF_BS  100352u
#define SMEM_SZ 101376

template<int NACT>
__device__ __forceinline__ void run_main(
    char* smem, const char* gw, bool ldr, uint32_t wdst,
    uint32_t c0, uint32_t c1, uint32_t aBaseH,
    uint32_t bBase, int warp_m, int warp_n, int l)
{
    constexpr int NSLAB = NACT >> 5;
    const int tc = l & 3;

    // bias cache (step-invariant)
    const float* bsp = (const float*)(smem + OFF_BS);
    float bias_r[4][2][2];
#pragma unroll
    for (int p = 0; p < 4; p++) {
        if (NACT == 256 || p * 64 + warp_n * 16 < NACT) {
#pragma unroll
            for (int hn = 0; hn < 2; hn++) {
                int j = p * 64 + warp_n * 16 + hn * 8 + tc * 2;
                bias_r[p][hn][0] = bsp[j];
                bias_r[p][hn][1] = bsp[j + 1];
            }
        }
    }

    float acc[2][8][4];
    uint32_t buf = 0;

    for (int step = 0; step < STEPS; step++) {
#pragma unroll
        for (int i = 0; i < 2; i++)
#pragma unroll
            for (int jn = 0; jn < 8; jn++)
#pragma unroll
                for (int r = 0; r < 4; r++) acc[i][jn][r] = 0.0f;

#pragma unroll
        for (int s = 0; s < NSLAB; s++) {
            bool last = (step == STEPS - 1) && (s == NSLAB - 1);
            if (!last && ldr) {
                int sn = (s + 1 == NSLAB) ? 0 : s + 1;
                const char* src = gw + (size_t)sn * 16384;
                uint32_t d = wdst + (buf ^ 1u) * WBUF;
                cp16(d + c0, src);
                cp16(d + c1, src + 16);
                cp16(d + WSUB + c0, src + 8192);
                cp16(d + WSUB + c1, src + 8192 + 16);
            }
            asm volatile("cp.async.commit_group;" ::: "memory");

            const uint32_t wOff = buf * WBUF;
#pragma unroll
            for (int kk = 0; kk < 2; kk++) {
                const uint32_t aoff = (uint32_t)(s * 64 + kk * 32);
                uint32_t aH0[4], aH1[4];
                LDSM4(aH0, aBaseH + aoff);
                LDSM4(aH1, aBaseH + 8448 + aoff);   // +16 rows * 528
                const uint32_t kOff = wOff + (uint32_t)kk * WSUB;
#pragma unroll
                for (int p = 0; p < 4; p++) {
                    if (NACT == 256 || p * 64 + warp_n * 16 < NACT) {
                        uint32_t bW[4];
                        LDSM4(bW, bBase + kOff + (uint32_t)(p * 64 + warp_n * 16) * 32);
                        MMA16816(acc[0][2 * p],     aH0, bW[0], bW[1]);
                        MMA16816(acc[0][2 * p + 1], aH0, bW[2], bW[3]);
                        MMA16816(acc[1][2 * p],     aH1, bW[0], bW[1]);
                        MMA16816(acc[1][2 * p + 1], aH1, bW[2], bW[3]);
                    }
                }
            }

            if (s < NSLAB - 1) {
                asm volatile("cp.async.wait_group 0;" ::: "memory");
                __syncthreads();
            }
            buf ^= 1u;
        }

        // ---- epilogue: x += relu(acc + b), re-split fp16 pair (exact state) ----
        __syncthreads();
        int q4 = l >> 2;
#pragma unroll
        for (int mt = 0; mt < 2; mt++) {
            int mrow = warp_m * 32 + mt * 16 + q4;
#pragma unroll
            for (int p = 0; p < 4; p++) {
                if (!(NACT == 256 || p * 64 + warp_n * 16 < NACT)) continue;
#pragma unroll
                for (int hn = 0; hn < 2; hn++) {
                    int j = p * 64 + warp_n * 16 + hn * 8 + tc * 2;
                    float b0 = bias_r[p][hn][0], b1 = bias_r[p][hn][1];
                    float* a4 = acc[mt][2 * p + hn];
#pragma unroll
                    for (int half = 0; half < 2; half++) {
                        int m = mrow + half * 8;
                        uint32_t off = (uint32_t)m * XSTR + (uint32_t)j * 2;
                        uint32_t h  = *(uint32_t*)(smem + OFF_XH + off);
                        uint32_t lo = *(uint32_t*)(smem + OFF_XL + off);
                        __half2 H = *(__half2*)&h;
                        __half2 L = *(__half2*)&lo;
                        float x0 = __half2float(H.x) + __half2float(L.x)
                                   + fmaxf(a4[half * 2]     + b0, 0.0f);
                        float x1 = __half2float(H.y) + __half2float(L.y)
                                   + fmaxf(a4[half * 2 + 1] + b1, 0.0f);
                        uint32_t nh, nl;
                        split2h(x0, x1, nh, nl);
                        *(uint32_t*)(smem + OFF_XH + off) = nh;
                        *(uint32_t*)(smem + OFF_XL + off) = nl;
                    }
                }
            }
        }
        asm volatile("cp.async.wait_group 0;" ::: "memory");
        __syncthreads();
    }
}

__global__ __launch_bounds__(NTH, 2)
void recur_kernel(const float* __restrict__ x_in, float* __restrict__ out) {
    extern __shared__ char smem[];
    uint32_t sb = smem_u32(smem);
    int n  = blockIdx.y;
    int m0 = blockIdx.x * MT;
    int t  = threadIdx.x;
    int l  = t & 31;
    int wid = t >> 5;
    int warp_m = wid >> 2;
    int warp_n = wid & 3;

    int nact = g_nact[n];
    ((float*)(smem + OFF_BS))[t] = g_bias[n * D_ + t];

    // ---- initial x load + fp16 pair split ----
    {
        int m = t >> 2, q = t & 3;
        const float4* src =
            (const float4*)(x_in + ((size_t)(m0 + m) * N_ + n) * D_) + q * 16;
        char* rowH = smem + OFF_XH + m * XSTR;
        char* rowL = smem + OFF_XL + m * XSTR;
#pragma unroll
        for (int c = 0; c < 16; c++) {
            float4 v = src[c];
            int k = q * 64 + c * 4;
            uint32_t h0, l0, h1, l1;
            split2h(v.x, v.y, h0, l0);
            split2h(v.z, v.w, h1, l1);
            *(uint32_t*)(rowH + k * 2)     = h0;
            *(uint32_t*)(rowL + k * 2)     = l0;
            *(uint32_t*)(rowH + k * 2 + 4) = h1;
            *(uint32_t*)(rowL + k * 2 + 4) = l1;
        }
    }

    const bool ldr = (t < nact);
    const char* gw = (const char*)g_w + ((size_t)n * 16 * D_ + t) * 32;
    const uint32_t swz = ((uint32_t)(t >> 2) & 1u) * 16u;
    const uint32_t c0 = swz, c1 = 16u - swz;
    const uint32_t wdst = sb + OFF_W + (uint32_t)t * 32;

    // preload slab 0 -> buf 0
    if (ldr) {
        cp16(wdst + c0, gw);
        cp16(wdst + c1, gw + 16);
        cp16(wdst + WSUB + c0, gw + 8192);
        cp16(wdst + WSUB + c1, gw + 8192 + 16);
    }
    asm volatile("cp.async.commit_group;" ::: "memory");
    asm volatile("cp.async.wait_group 0;" ::: "memory");
    __syncthreads();

    const uint32_t aBaseH = sb + OFF_XH + (uint32_t)(warp_m * 32 + (l & 15)) * XSTR
                            + (uint32_t)(l >> 4) * 16;
    const int br = (l & 7) + ((l >> 4) & 1) * 8;
    const int bh = (l >> 3) & 1;
    const uint32_t bBase = sb + OFF_W + (uint32_t)br * 32
                           + (uint32_t)((bh ^ ((br >> 2) & 1)) * 16);

    switch (nact) {
        case 128: run_main<128>(smem, gw, ldr, wdst, c0, c1, aBaseH, bBase, warp_m, warp_n, l); break;
        case 160: run_main<160>(smem, gw, ldr, wdst, c0, c1, aBaseH, bBase, warp_m, warp_n, l); break;
        case 192: run_main<192>(smem, gw, ldr, wdst, c0, c1, aBaseH, bBase, warp_m, warp_n, l); break;
        case 224: run_main<224>(smem, gw, ldr, wdst, c0, c1, aBaseH, bBase, warp_m, warp_n, l); break;
        default:  run_main<256>(smem, gw, ldr, wdst, c0, c1, aBaseH, bBase, warp_m, warp_n, l); break;
    }

    // ---- final store: x = hi + lo ----
    {
        int m = t >> 2, q = t & 3;
        float4* dst = (float4*)(out + ((size_t)(m0 + m) * N_ + n) * D_) + q * 16;
        const char* rowH = smem + OFF_XH + m * XSTR;
        const char* rowL = smem + OFF_XL + m * XSTR;
#pragma unroll
        for (int c = 0; c < 16; c++) {
            int k = q * 64 + c * 4;
            uint32_t h0  = *(const uint32_t*)(rowH + k * 2);
            uint32_t l0  = *(const uint32_t*)(rowL + k * 2);
            uint32_t h1  = *(const uint32_t*)(rowH + k * 2 + 4);
            uint32_t l1  = *(const uint32_t*)(rowL + k * 2 + 4);
            __half2 H0 = *(__half2*)&h0, L0 = *(__half2*)&l0;
            __half2 H1 = *(__half2*)&h1, L1 = *(__half2*)&l1;
            float4 v;
            v.x = __half2float(H0.x) + __half2float(L0.x);
            v.y = __half2float(H0.y) + __half2float(L0.y);
            v.z = __half2float(H1.x) + __half2float(L1.x);
            v.w = __half2float(H1.y) + __half2float(L1.y);
            dst[c] = v;
        }
    }
}

// ---------------------------------------------------------------------------
extern "C" void kernel_launch(void* const* d_in, const int* in_sizes, int n_in,
                              void* d_out, int out_size) {
    const float* x  = (const float*)d_in[0];
    const float* w  = (const float*)d_in[1];
    const float* b  = (const float*)d_in[2];
    const float* wm = (const float*)d_in[3];
    const float* bm = (const float*)d_in[4];
    float* out = (float*)d_out;

    prep_kernel<<<dim3(N_, 16), 256>>>(w, wm, b, bm);

    cudaFuncSetAttribute(recur_kernel,
                         cudaFuncAttributeMaxDynamicSharedMemorySize, SMEM_SZ);
    recur_kernel<<<dim3(B_ / MT, N_), NTH, SMEM_SZ>>>(x, out);
}

// round 12
// speedup vs baseline: 1.4846x; 1.2449x over previous
#include <cuda_runtime.h>
#include <cuda_fp16.h>
#include <cstdint>

#define B_ 2048
#define N_ 64
#define D_ 256
#define MT 64
#define NTH 256
#define STEPS 4

// ---------------------------------------------------------------------------
// w image (fp16, masked), slab-major: [n][slab16(16)][row(256)][16k*fp16=32B]
// ---------------------------------------------------------------------------
__device__ uint32_t g_w[(size_t)N_ * 16 * D_ * 8];   // 8 MB
__device__ float    g_bias[N_ * D_];
__device__ int      g_nact[N_];

__device__ __forceinline__ uint32_t smem_u32(const void* p) {
    uint32_t a;
    asm("{ .reg .u64 t; cvta.to.shared.u64 t, %1; cvt.u32.u64 %0, t; }"
        : "=r"(a) : "l"(p));
    return a;
}

__device__ __forceinline__ void cp16(uint32_t dst, const void* src) {
    asm volatile("cp.async.ca.shared.global [%0], [%1], 16;"
                 :: "r"(dst), "l"(src) : "memory");
}

#define LDSM4(r, addr) \
    asm volatile("ldmatrix.sync.aligned.m8n8.x4.shared.b16 {%0,%1,%2,%3}, [%4];" \
        : "=r"((r)[0]), "=r"((r)[1]), "=r"((r)[2]), "=r"((r)[3]) : "r"(addr))

#define MMA16816(d, a, b0, b1) \
    asm volatile("mma.sync.aligned.m16n8k16.row.col.f32.f16.f16.f32 " \
        "{%0,%1,%2,%3}, {%4,%5,%6,%7}, {%8,%9}, {%0,%1,%2,%3};" \
        : "+f"((d)[0]), "+f"((d)[1]), "+f"((d)[2]), "+f"((d)[3]) \
        : "r"((a)[0]), "r"((a)[1]), "r"((a)[2]), "r"((a)[3]), "r"(b0), "r"(b1))

// ---------------------------------------------------------------------------
// Fused prep: masked fp16 w image; block.y==0 also does bias + nact.
// ---------------------------------------------------------------------------
__global__ void prep_kernel(const float* __restrict__ w,
                            const float* __restrict__ wm,
                            const float* __restrict__ b,
                            const float* __restrict__ bm) {
    int n = blockIdx.x;
    int t = threadIdx.x;
    int j = blockIdx.y * 16 + (t >> 4);
    int c = t & 15;
    const float4* wp = (const float4*)(w  + ((size_t)n * D_ + j) * D_) + c * 4;
    const float4* mp = (const float4*)(wm + ((size_t)n * D_ + j) * D_) + c * 4;
    uint32_t* o = g_w + (((size_t)n * 16 + c) * D_ + j) * 8;
#pragma unroll
    for (int i4 = 0; i4 < 4; i4++) {
        float4 a = wp[i4];
        float4 m = mp[i4];
        __half2 h0 = __floats2half2_rn(a.x * m.x, a.y * m.y);
        __half2 h1 = __floats2half2_rn(a.z * m.z, a.w * m.w);
        o[i4 * 2]     = *reinterpret_cast<uint32_t*>(&h0);
        o[i4 * 2 + 1] = *reinterpret_cast<uint32_t*>(&h1);
    }
    if (blockIdx.y == 0) {
        __shared__ int cnt;
        if (t == 0) cnt = 0;
        __syncthreads();
        float m = bm[n * D_ + t];
        g_bias[n * D_ + t] = b[n * D_ + t] * m;
        unsigned ballot = __ballot_sync(0xFFFFFFFFu, m != 0.0f);
        if ((t & 31) == 0) atomicAdd(&cnt, __popc(ballot));
        __syncthreads();
        if (t == 0) g_nact[n] = cnt;
    }
}

// ---------------------------------------------------------------------------
// MT=64, occ 2. x state = plain fp16 tile (single stream); MMA sees the exact
// state. Per-step fp16 state rounding (~1.4e-4 RMS) x sqrt(4) + w quant
// 1.6e-4 => ~3.2e-4 total, under the 1e-3 gate.
// ---------------------------------------------------------------------------
#define XSTR    528
#define OFF_XH  0u
#define OFF_W   33792u
#define WBUF    16384u
#define WSUB    8192u
#define OFF_BS  66560u
#define SMEM_SZ 67584

template<int NACT>
__device__ __forceinline__ void run_main(
    char* smem, const char* gw, bool ldr, uint32_t wdst,
    uint32_t c0, uint32_t c1, uint32_t aBaseH,
    uint32_t bBase, int warp_m, int warp_n, int l)
{
    constexpr int NSLAB = NACT >> 5;
    const int tc = l & 3;

    // bias cache (step-invariant)
    const float* bsp = (const float*)(smem + OFF_BS);
    float bias_r[4][2][2];
#pragma unroll
    for (int p = 0; p < 4; p++) {
        if (NACT == 256 || p * 64 + warp_n * 16 < NACT) {
#pragma unroll
            for (int hn = 0; hn < 2; hn++) {
                int j = p * 64 + warp_n * 16 + hn * 8 + tc * 2;
                bias_r[p][hn][0] = bsp[j];
                bias_r[p][hn][1] = bsp[j + 1];
            }
        }
    }

    float acc[2][8][4];
    uint32_t buf = 0;

    for (int step = 0; step < STEPS; step++) {
#pragma unroll
        for (int i = 0; i < 2; i++)
#pragma unroll
            for (int jn = 0; jn < 8; jn++)
#pragma unroll
                for (int r = 0; r < 4; r++) acc[i][jn][r] = 0.0f;

#pragma unroll
        for (int s = 0; s < NSLAB; s++) {
            bool last = (step == STEPS - 1) && (s == NSLAB - 1);
            if (!last && ldr) {
                int sn = (s + 1 == NSLAB) ? 0 : s + 1;
                const char* src = gw + (size_t)sn * 16384;
                uint32_t d = wdst + (buf ^ 1u) * WBUF;
                cp16(d + c0, src);
                cp16(d + c1, src + 16);
                cp16(d + WSUB + c0, src + 8192);
                cp16(d + WSUB + c1, src + 8192 + 16);
            }
            asm volatile("cp.async.commit_group;" ::: "memory");

            const uint32_t wOff = buf * WBUF;
#pragma unroll
            for (int kk = 0; kk < 2; kk++) {
                const uint32_t aoff = (uint32_t)(s * 64 + kk * 32);
                uint32_t aH0[4], aH1[4];
                LDSM4(aH0, aBaseH + aoff);
                LDSM4(aH1, aBaseH + 8448 + aoff);   // +16 rows * 528
                const uint32_t kOff = wOff + (uint32_t)kk * WSUB;
#pragma unroll
                for (int p = 0; p < 4; p++) {
                    if (NACT == 256 || p * 64 + warp_n * 16 < NACT) {
                        uint32_t bW[4];
                        LDSM4(bW, bBase + kOff + (uint32_t)(p * 64 + warp_n * 16) * 32);
                        MMA16816(acc[0][2 * p],     aH0, bW[0], bW[1]);
                        MMA16816(acc[0][2 * p + 1], aH0, bW[2], bW[3]);
                        MMA16816(acc[1][2 * p],     aH1, bW[0], bW[1]);
                        MMA16816(acc[1][2 * p + 1], aH1, bW[2], bW[3]);
                    }
                }
            }

            if (s < NSLAB - 1) {
                asm volatile("cp.async.wait_group 0;" ::: "memory");
                __syncthreads();
            }
            buf ^= 1u;
        }

        // ---- epilogue: x = fp16(x + relu(acc + b)) ----
        __syncthreads();
        int q4 = l >> 2;
#pragma unroll
        for (int mt = 0; mt < 2; mt++) {
            int mrow = warp_m * 32 + mt * 16 + q4;
#pragma unroll
            for (int p = 0; p < 4; p++) {
                if (!(NACT == 256 || p * 64 + warp_n * 16 < NACT)) continue;
#pragma unroll
                for (int hn = 0; hn < 2; hn++) {
                    int j = p * 64 + warp_n * 16 + hn * 8 + tc * 2;
                    float b0 = bias_r[p][hn][0], b1 = bias_r[p][hn][1];
                    float* a4 = acc[mt][2 * p + hn];
#pragma unroll
                    for (int half = 0; half < 2; half++) {
                        int m = mrow + half * 8;
                        uint32_t off = (uint32_t)m * XSTR + (uint32_t)j * 2;
                        uint32_t h = *(uint32_t*)(smem + OFF_XH + off);
                        __half2 H = *(__half2*)&h;
                        float x0 = __half2float(H.x)
                                   + fmaxf(a4[half * 2]     + b0, 0.0f);
                        float x1 = __half2float(H.y)
                                   + fmaxf(a4[half * 2 + 1] + b1, 0.0f);
                        __half2 Nh = __floats2half2_rn(x0, x1);
                        *(uint32_t*)(smem + OFF_XH + off) =
                            *reinterpret_cast<uint32_t*>(&Nh);
                    }
                }
            }
        }
        asm volatile("cp.async.wait_group 0;" ::: "memory");
        __syncthreads();
    }
}

__global__ __launch_bounds__(NTH, 2)
void recur_kernel(const float* __restrict__ x_in, float* __restrict__ out) {
    extern __shared__ char smem[];
    uint32_t sb = smem_u32(smem);
    int n  = blockIdx.y;
    int m0 = blockIdx.x * MT;
    int t  = threadIdx.x;
    int l  = t & 31;
    int wid = t >> 5;
    int warp_m = wid >> 2;
    int warp_n = wid & 3;

    int nact = g_nact[n];
    ((float*)(smem + OFF_BS))[t] = g_bias[n * D_ + t];

    // ---- initial x load -> fp16 tile ----
    {
        int m = t >> 2, q = t & 3;
        const float4* src =
            (const float4*)(x_in + ((size_t)(m0 + m) * N_ + n) * D_) + q * 16;
        char* rowH = smem + OFF_XH + m * XSTR;
#pragma unroll
        for (int c = 0; c < 16; c++) {
            float4 v = src[c];
            int k = q * 64 + c * 4;
            __half2 h0 = __floats2half2_rn(v.x, v.y);
            __half2 h1 = __floats2half2_rn(v.z, v.w);
            *(uint32_t*)(rowH + k * 2)     = *reinterpret_cast<uint32_t*>(&h0);
            *(uint32_t*)(rowH + k * 2 + 4) = *reinterpret_cast<uint32_t*>(&h1);
        }
    }

    const bool ldr = (t < nact);
    const char* gw = (const char*)g_w + ((size_t)n * 16 * D_ + t) * 32;
    const uint32_t swz = ((uint32_t)(t >> 2) & 1u) * 16u;
    const uint32_t c0 = swz, c1 = 16u - swz;
    const uint32_t wdst = sb + OFF_W + (uint32_t)t * 32;

    // preload slab 0 -> buf 0
    if (ldr) {
        cp16(wdst + c0, gw);
        cp16(wdst + c1, gw + 16);
        cp16(wdst + WSUB + c0, gw + 8192);
        cp16(wdst + WSUB + c1, gw + 8192 + 16);
    }
    asm volatile("cp.async.commit_group;" ::: "memory");
    asm volatile("cp.async.wait_group 0;" ::: "memory");
    __syncthreads();

    const uint32_t aBaseH = sb + OFF_XH + (uint32_t)(warp_m * 32 + (l & 15)) * XSTR
                            + (uint32_t)(l >> 4) * 16;
    const int br = (l & 7) + ((l >> 4) & 1) * 8;
    const int bh = (l >> 3) & 1;
    const uint32_t bBase = sb + OFF_W + (uint32_t)br * 32
                           + (uint32_t)((bh ^ ((br >> 2) & 1)) * 16);

    switch (nact) {
        case 128: run_main<128>(smem, gw, ldr, wdst, c0, c1, aBaseH, bBase, warp_m, warp_n, l); break;
        case 160: run_main<160>(smem, gw, ldr, wdst, c0, c1, aBaseH, bBase, warp_m, warp_n, l); break;
        case 192: run_main<192>(smem, gw, ldr, wdst, c0, c1, aBaseH, bBase, warp_m, warp_n, l); break;
        case 224: run_main<224>(smem, gw, ldr, wdst, c0, c1, aBaseH, bBase, warp_m, warp_n, l); break;
        default:  run_main<256>(smem, gw, ldr, wdst, c0, c1, aBaseH, bBase, warp_m, warp_n, l); break;
    }

    // ---- final store: fp16 -> fp32 ----
    {
        int m = t >> 2, q = t & 3;
        float4* dst = (float4*)(out + ((size_t)(m0 + m) * N_ + n) * D_) + q * 16;
        const char* rowH = smem + OFF_XH + m * XSTR;
#pragma unroll
        for (int c = 0; c < 16; c++) {
            int k = q * 64 + c * 4;
            uint32_t h0 = *(const uint32_t*)(rowH + k * 2);
            uint32_t h1 = *(const uint32_t*)(rowH + k * 2 + 4);
            __half2 H0 = *(__half2*)&h0, H1 = *(__half2*)&h1;
            float4 v;
            v.x = __half2float(H0.x);
            v.y = __half2float(H0.y);
            v.z = __half2float(H1.x);
            v.w = __half2float(H1.y);
            dst[c] = v;
        }
    }
}

// ---------------------------------------------------------------------------
extern "C" void kernel_launch(void* const* d_in, const int* in_sizes, int n_in,
                              void* d_out, int out_size) {
    const float* x  = (const float*)d_in[0];
    const float* w  = (const float*)d_in[1];
    const float* b  = (const float*)d_in[2];
    const float* wm = (const float*)d_in[3];
    const float* bm = (const float*)d_in[4];
    float* out = (float*)d_out;

    prep_kernel<<<dim3(N_, 16), 256>>>(w, wm, b, bm);

    cudaFuncSetAttribute(recur_kernel,
                         cudaFuncAttributeMaxDynamicSharedMemorySize, SMEM_SZ);
    recur_kernel<<<dim3(B_ / MT, N_), NTH, SMEM_SZ>>>(x, out);
}

// round 13
// speedup vs baseline: 1.6727x; 1.1267x over previous
#include <cuda_runtime.h>
#include <cuda_fp16.h>
#include <cstdint>

#define B_ 2048
#define N_ 64
#define D_ 256
#define MT 64
#define NTH 256
#define STEPS 4

// ---------------------------------------------------------------------------
// w image in MMA-register layout:
//   g_wB[n][kk(16)][q(16)] = 512B block = n16 x k16 tile-pair.
//   lane l bytes [16l,16l+16): {B[na][k0,k0+1], B[na][k0+8,k0+9],
//                               B[nb][k0,k0+1], B[nb][k0+8,k0+9]}
//   na = 16q + (l>>2), nb = na+8, k0 = 16kk + 2(l&3);  B[n][k] = w_masked[n][k]
// ---------------------------------------------------------------------------
__device__ uint32_t g_wB[(size_t)N_ * 16 * 16 * 128];   // 8 MB
__device__ float    g_bias[N_ * D_];
__device__ int      g_nact[N_];

__device__ __forceinline__ uint32_t smem_u32(const void* p) {
    uint32_t a;
    asm("{ .reg .u64 t; cvta.to.shared.u64 t, %1; cvt.u32.u64 %0, t; }"
        : "=r"(a) : "l"(p));
    return a;
}

#define LDSM4(r, addr) \
    asm volatile("ldmatrix.sync.aligned.m8n8.x4.shared.b16 {%0,%1,%2,%3}, [%4];" \
        : "=r"((r)[0]), "=r"((r)[1]), "=r"((r)[2]), "=r"((r)[3]) : "r"(addr))

#define MMA16816(d, a, b0, b1) \
    asm volatile("mma.sync.aligned.m16n8k16.row.col.f32.f16.f16.f32 " \
        "{%0,%1,%2,%3}, {%4,%5,%6,%7}, {%8,%9}, {%0,%1,%2,%3};" \
        : "+f"((d)[0]), "+f"((d)[1]), "+f"((d)[2]), "+f"((d)[3]) \
        : "r"((a)[0]), "r"((a)[1]), "r"((a)[2]), "r"((a)[3]), "r"(b0), "r"(b1))

// ---------------------------------------------------------------------------
// Prep: masked fp16 w -> register-layout image. grid (64, 16=kk), 512 thr.
// thread: q = t>>5, lane l = t&31. blockIdx.y==0 also does bias + nact.
// ---------------------------------------------------------------------------
__global__ void prep_kernel(const float* __restrict__ w,
                            const float* __restrict__ wm,
                            const float* __restrict__ b,
                            const float* __restrict__ bm) {
    int n  = blockIdx.x;
    int kk = blockIdx.y;
    int t  = threadIdx.x;
    int q  = t >> 5;
    int l  = t & 31;
    int na = 16 * q + (l >> 2);
    int nb = na + 8;
    int k0 = 16 * kk + 2 * (l & 3);

    const float* wa = w  + ((size_t)n * D_ + na) * D_;
    const float* ma = wm + ((size_t)n * D_ + na) * D_;
    const float* wb = w  + ((size_t)n * D_ + nb) * D_;
    const float* mb = wm + ((size_t)n * D_ + nb) * D_;

    __half2 h0 = __floats2half2_rn(wa[k0] * ma[k0],     wa[k0+1] * ma[k0+1]);
    __half2 h1 = __floats2half2_rn(wa[k0+8] * ma[k0+8], wa[k0+9] * ma[k0+9]);
    __half2 h2 = __floats2half2_rn(wb[k0] * mb[k0],     wb[k0+1] * mb[k0+1]);
    __half2 h3 = __floats2half2_rn(wb[k0+8] * mb[k0+8], wb[k0+9] * mb[k0+9]);

    uint4 v;
    v.x = *reinterpret_cast<uint32_t*>(&h0);
    v.y = *reinterpret_cast<uint32_t*>(&h1);
    v.z = *reinterpret_cast<uint32_t*>(&h2);
    v.w = *reinterpret_cast<uint32_t*>(&h3);
    *reinterpret_cast<uint4*>(
        g_wB + (((size_t)n * 16 + kk) * 16 + q) * 128 + l * 4) = v;

    if (blockIdx.y == 0 && t < D_) {
        __shared__ int cnt;
        if (t == 0) cnt = 0;
        __syncthreads();
        float m = bm[n * D_ + t];
        g_bias[n * D_ + t] = b[n * D_ + t] * m;
        unsigned ballot = __ballot_sync(0xFFFFFFFFu, m != 0.0f);
        if ((t & 31) == 0) atomicAdd(&cnt, __popc(ballot));
        __syncthreads();
        if (t == 0) g_nact[n] = cnt;
    } else if (blockIdx.y == 0) {
        __syncthreads();
        __syncthreads();
    }
}

// ---------------------------------------------------------------------------
// Main. B operands via coalesced __ldg LDG.128 from register-layout image
// (L1-resident after step 1). No smem w staging, no cp.async, 2 barriers/step.
// x state = fp16 tile in smem. Numerics identical to R12.
// ---------------------------------------------------------------------------
#define XSTR    528
#define OFF_XH  0u
#define OFF_BS  33792u
#define SMEM_SZ 34816

template<int NACT>
__device__ __forceinline__ void run_main(
    char* smem, const uint4* __restrict__ gB, uint32_t aBaseH,
    int warp_m, int warp_n, int l)
{
    constexpr int NKK = NACT >> 4;
    const int tc = l & 3;

    // bias cache (step-invariant)
    const float* bsp = (const float*)(smem + OFF_BS);
    float bias_r[4][2][2];
#pragma unroll
    for (int p = 0; p < 4; p++) {
        if (NACT == 256 || p * 64 + warp_n * 16 < NACT) {
#pragma unroll
            for (int hn = 0; hn < 2; hn++) {
                int j = p * 64 + warp_n * 16 + hn * 8 + tc * 2;
                bias_r[p][hn][0] = bsp[j];
                bias_r[p][hn][1] = bsp[j + 1];
            }
        }
    }

    float acc[2][8][4];

    for (int step = 0; step < STEPS; step++) {
#pragma unroll
        for (int i = 0; i < 2; i++)
#pragma unroll
            for (int jn = 0; jn < 8; jn++)
#pragma unroll
                for (int r = 0; r < 4; r++) acc[i][jn][r] = 0.0f;

#pragma unroll
        for (int kk = 0; kk < NKK; kk++) {
            const uint32_t aoff = (uint32_t)kk * 32;
            uint32_t aH0[4], aH1[4];
            LDSM4(aH0, aBaseH + aoff);
            LDSM4(aH1, aBaseH + 8448 + aoff);   // +16 rows * 528
#pragma unroll
            for (int p = 0; p < 4; p++) {
                if (NACT == 256 || p * 64 + warp_n * 16 < NACT) {
                    const int q = p * 4 + warp_n;
                    uint4 bw = __ldg(gB + (size_t)(kk * 16 + q) * 32 + l);
                    MMA16816(acc[0][2 * p],     aH0, bw.x, bw.y);
                    MMA16816(acc[0][2 * p + 1], aH0, bw.z, bw.w);
                    MMA16816(acc[1][2 * p],     aH1, bw.x, bw.y);
                    MMA16816(acc[1][2 * p + 1], aH1, bw.z, bw.w);
                }
            }
        }

        // ---- epilogue: x = fp16(x + relu(acc + b)) ----
        __syncthreads();
        int q4 = l >> 2;
#pragma unroll
        for (int mt = 0; mt < 2; mt++) {
            int mrow = warp_m * 32 + mt * 16 + q4;
#pragma unroll
            for (int p = 0; p < 4; p++) {
                if (!(NACT == 256 || p * 64 + warp_n * 16 < NACT)) continue;
#pragma unroll
                for (int hn = 0; hn < 2; hn++) {
                    int j = p * 64 + warp_n * 16 + hn * 8 + tc * 2;
                    float b0 = bias_r[p][hn][0], b1 = bias_r[p][hn][1];
                    float* a4 = acc[mt][2 * p + hn];
#pragma unroll
                    for (int half = 0; half < 2; half++) {
                        int m = mrow + half * 8;
                        uint32_t off = (uint32_t)m * XSTR + (uint32_t)j * 2;
                        uint32_t h = *(uint32_t*)(smem + OFF_XH + off);
                        __half2 H = *(__half2*)&h;
                        float x0 = __half2float(H.x)
                                   + fmaxf(a4[half * 2]     + b0, 0.0f);
                        float x1 = __half2float(H.y)
                                   + fmaxf(a4[half * 2 + 1] + b1, 0.0f);
                        __half2 Nh = __floats2half2_rn(x0, x1);
                        *(uint32_t*)(smem + OFF_XH + off) =
                            *reinterpret_cast<uint32_t*>(&Nh);
                    }
                }
            }
        }
        __syncthreads();
    }
}

__global__ __launch_bounds__(NTH, 2)
void recur_kernel(const float* __restrict__ x_in, float* __restrict__ out) {
    extern __shared__ char smem[];
    uint32_t sb = smem_u32(smem);
    int n  = blockIdx.y;
    int m0 = blockIdx.x * MT;
    int t  = threadIdx.x;
    int l  = t & 31;
    int wid = t >> 5;
    int warp_m = wid >> 2;
    int warp_n = wid & 3;

    int nact = g_nact[n];
    ((float*)(smem + OFF_BS))[t] = g_bias[n * D_ + t];

    // ---- initial x load -> fp16 tile ----
    {
        int m = t >> 2, q = t & 3;
        const float4* src =
            (const float4*)(x_in + ((size_t)(m0 + m) * N_ + n) * D_) + q * 16;
        char* rowH = smem + OFF_XH + m * XSTR;
#pragma unroll
        for (int c = 0; c < 16; c++) {
            float4 v = src[c];
            int k = q * 64 + c * 4;
            __half2 h0 = __floats2half2_rn(v.x, v.y);
            __half2 h1 = __floats2half2_rn(v.z, v.w);
            *(uint32_t*)(rowH + k * 2)     = *reinterpret_cast<uint32_t*>(&h0);
            *(uint32_t*)(rowH + k * 2 + 4) = *reinterpret_cast<uint32_t*>(&h1);
        }
    }
    __syncthreads();

    const uint32_t aBaseH = sb + OFF_XH + (uint32_t)(warp_m * 32 + (l & 15)) * XSTR
                            + (uint32_t)(l >> 4) * 16;
    const uint4* gB = reinterpret_cast<const uint4*>(g_wB) + (size_t)n * 16 * 16 * 32;

    switch (nact) {
        case 128: run_main<128>(smem, gB, aBaseH, warp_m, warp_n, l); break;
        case 160: run_main<160>(smem, gB, aBaseH, warp_m, warp_n, l); break;
        case 192: run_main<192>(smem, gB, aBaseH, warp_m, warp_n, l); break;
        case 224: run_main<224>(smem, gB, aBaseH, warp_m, warp_n, l); break;
        default:  run_main<256>(smem, gB, aBaseH, warp_m, warp_n, l); break;
    }

    // ---- final store: fp16 -> fp32 ----
    {
        int m = t >> 2, q = t & 3;
        float4* dst = (float4*)(out + ((size_t)(m0 + m) * N_ + n) * D_) + q * 16;
        const char* rowH = smem + OFF_XH + m * XSTR;
#pragma unroll
        for (int c = 0; c < 16; c++) {
            int k = q * 64 + c * 4;
            uint32_t h0 = *(const uint32_t*)(rowH + k * 2);
            uint32_t h1 = *(const uint32_t*)(rowH + k * 2 + 4);
            __half2 H0 = *(__half2*)&h0, H1 = *(__half2*)&h1;
            float4 v;
            v.x = __half2float(H0.x);
            v.y = __half2float(H0.y);
            v.z = __half2float(H1.x);
            v.w = __half2float(H1.y);
            dst[c] = v;
        }
    }
}

// ---------------------------------------------------------------------------
extern "C" void kernel_launch(void* const* d_in, const int* in_sizes, int n_in,
                              void* d_out, int out_size) {
    const float* x  = (const float*)d_in[0];
    const float* w  = (const float*)d_in[1];
    const float* b  = (const float*)d_in[2];
    const float* wm = (const float*)d_in[3];
    const float* bm = (const float*)d_in[4];
    float* out = (float*)d_out;

    prep_kernel<<<dim3(N_, 16), 512>>>(w, wm, b, bm);

    cudaFuncSetAttribute(recur_kernel,
                         cudaFuncAttributeMaxDynamicSharedMemorySize, SMEM_SZ);
    recur_kernel<<<dim3(B_ / MT, N_), NTH, SMEM_SZ>>>(x, out);
}

// round 14
// speedup vs baseline: 1.6784x; 1.0034x over previous
#include <cuda_runtime.h>
#include <cuda_fp16.h>
#include <cstdint>

#define B_ 2048
#define N_ 64
#define D_ 256
#define MT 64
#define NTH 256
#define STEPS 4

// ---------------------------------------------------------------------------
// w image in MMA-register layout:
//   g_wB[n][kk(16)][q(16)] = 512B block = n16 x k16 tile-pair.
// ---------------------------------------------------------------------------
__device__ uint32_t g_wB[(size_t)N_ * 16 * 16 * 128];   // 8 MB
__device__ float    g_bias[N_ * D_];
__device__ int      g_nact[N_];

__device__ __forceinline__ uint32_t smem_u32(const void* p) {
    uint32_t a;
    asm("{ .reg .u64 t; cvta.to.shared.u64 t, %1; cvt.u32.u64 %0, t; }"
        : "=r"(a) : "l"(p));
    return a;
}

#define LDSM4(r, addr) \
    asm volatile("ldmatrix.sync.aligned.m8n8.x4.shared.b16 {%0,%1,%2,%3}, [%4];" \
        : "=r"((r)[0]), "=r"((r)[1]), "=r"((r)[2]), "=r"((r)[3]) : "r"(addr))

#define STSM4(addr, r) \
    asm volatile("stmatrix.sync.aligned.m8n8.x4.shared.b16 [%0], {%1,%2,%3,%4};" \
        :: "r"(addr), "r"((r)[0]), "r"((r)[1]), "r"((r)[2]), "r"((r)[3]) : "memory")

#define MMA16816(d, a, b0, b1) \
    asm volatile("mma.sync.aligned.m16n8k16.row.col.f32.f16.f16.f32 " \
        "{%0,%1,%2,%3}, {%4,%5,%6,%7}, {%8,%9}, {%0,%1,%2,%3};" \
        : "+f"((d)[0]), "+f"((d)[1]), "+f"((d)[2]), "+f"((d)[3]) \
        : "r"((a)[0]), "r"((a)[1]), "r"((a)[2]), "r"((a)[3]), "r"(b0), "r"(b1))

// ---------------------------------------------------------------------------
// Prep: masked fp16 w -> register-layout image. grid (64, 16=kk), 512 thr.
// ---------------------------------------------------------------------------
__global__ void prep_kernel(const float* __restrict__ w,
                            const float* __restrict__ wm,
                            const float* __restrict__ b,
                            const float* __restrict__ bm) {
    int n  = blockIdx.x;
    int kk = blockIdx.y;
    int t  = threadIdx.x;
    int q  = t >> 5;
    int l  = t & 31;
    int na = 16 * q + (l >> 2);
    int nb = na + 8;
    int k0 = 16 * kk + 2 * (l & 3);

    const float* wa = w  + ((size_t)n * D_ + na) * D_;
    const float* ma = wm + ((size_t)n * D_ + na) * D_;
    const float* wb = w  + ((size_t)n * D_ + nb) * D_;
    const float* mb = wm + ((size_t)n * D_ + nb) * D_;

    __half2 h0 = __floats2half2_rn(wa[k0] * ma[k0],     wa[k0+1] * ma[k0+1]);
    __half2 h1 = __floats2half2_rn(wa[k0+8] * ma[k0+8], wa[k0+9] * ma[k0+9]);
    __half2 h2 = __floats2half2_rn(wb[k0] * mb[k0],     wb[k0+1] * mb[k0+1]);
    __half2 h3 = __floats2half2_rn(wb[k0+8] * mb[k0+8], wb[k0+9] * mb[k0+9]);

    uint4 v;
    v.x = *reinterpret_cast<uint32_t*>(&h0);
    v.y = *reinterpret_cast<uint32_t*>(&h1);
    v.z = *reinterpret_cast<uint32_t*>(&h2);
    v.w = *reinterpret_cast<uint32_t*>(&h3);
    *reinterpret_cast<uint4*>(
        g_wB + (((size_t)n * 16 + kk) * 16 + q) * 128 + l * 4) = v;

    if (blockIdx.y == 0 && t < D_) {
        __shared__ int cnt;
        if (t == 0) cnt = 0;
        __syncthreads();
        float m = bm[n * D_ + t];
        g_bias[n * D_ + t] = b[n * D_ + t] * m;
        unsigned ballot = __ballot_sync(0xFFFFFFFFu, m != 0.0f);
        if ((t & 31) == 0) atomicAdd(&cnt, __popc(ballot));
        __syncthreads();
        if (t == 0) g_nact[n] = cnt;
    } else if (blockIdx.y == 0) {
        __syncthreads();
        __syncthreads();
    }
}

// ---------------------------------------------------------------------------
// Main. B via coalesced LDG from register-layout image (L1-resident). x state
// = fp16 tile in smem. Epilogue uses ldmatrix/stmatrix fragment I/O:
// per (mt,p) 16x16 tile = 1 LDSM.x4 + 1 STSM.x4 (acc layout == frag layout).
// ---------------------------------------------------------------------------
#define XSTR    528
#define OFF_XH  0u
#define OFF_BS  33792u
#define SMEM_SZ 34816

template<int NACT>
__device__ __forceinline__ void run_main(
    char* smem, const uint4* __restrict__ gB, uint32_t aBaseH, uint32_t eBase,
    int warp_m, int warp_n, int l)
{
    constexpr int NKK = NACT >> 4;
    const int tc = l & 3;

    // bias cache (step-invariant)
    const float* bsp = (const float*)(smem + OFF_BS);
    float bias_r[4][2][2];
#pragma unroll
    for (int p = 0; p < 4; p++) {
        if (NACT == 256 || p * 64 + warp_n * 16 < NACT) {
#pragma unroll
            for (int hn = 0; hn < 2; hn++) {
                int j = p * 64 + warp_n * 16 + hn * 8 + tc * 2;
                bias_r[p][hn][0] = bsp[j];
                bias_r[p][hn][1] = bsp[j + 1];
            }
        }
    }

    float acc[2][8][4];

    for (int step = 0; step < STEPS; step++) {
#pragma unroll
        for (int i = 0; i < 2; i++)
#pragma unroll
            for (int jn = 0; jn < 8; jn++)
#pragma unroll
                for (int r = 0; r < 4; r++) acc[i][jn][r] = 0.0f;

#pragma unroll
        for (int kk = 0; kk < NKK; kk++) {
            const uint32_t aoff = (uint32_t)kk * 32;
            uint32_t aH0[4], aH1[4];
            LDSM4(aH0, aBaseH + aoff);
            LDSM4(aH1, aBaseH + 8448 + aoff);   // +16 rows * 528
#pragma unroll
            for (int p = 0; p < 4; p++) {
                if (NACT == 256 || p * 64 + warp_n * 16 < NACT) {
                    const int q = p * 4 + warp_n;
                    uint4 bw = __ldg(gB + (size_t)(kk * 16 + q) * 32 + l);
                    MMA16816(acc[0][2 * p],     aH0, bw.x, bw.y);
                    MMA16816(acc[0][2 * p + 1], aH0, bw.z, bw.w);
                    MMA16816(acc[1][2 * p],     aH1, bw.x, bw.y);
                    MMA16816(acc[1][2 * p + 1], aH1, bw.z, bw.w);
                }
            }
        }

        // ---- epilogue: x = fp16(x + relu(acc + b)) via LDSM/STSM ----
        __syncthreads();
#pragma unroll
        for (int mt = 0; mt < 2; mt++) {
            const uint32_t rowOff = (uint32_t)(warp_m * 32 + mt * 16) * XSTR;
#pragma unroll
            for (int p = 0; p < 4; p++) {
                if (!(NACT == 256 || p * 64 + warp_n * 16 < NACT)) continue;
                const int jb = p * 64 + warp_n * 16;
                const uint32_t addr = eBase + rowOff + (uint32_t)jb * 2;
                uint32_t o[4], v[4];
                LDSM4(o, addr);
#pragma unroll
                for (int i = 0; i < 4; i++) {
                    const int hn = i >> 1;            // matrix 0,1 -> hn0; 2,3 -> hn1
                    const int hf = i & 1;             // rows +0 / +8
                    const float* a4 = acc[mt][2 * p + hn];
                    __half2 O = *(__half2*)&o[i];
                    float x0 = __half2float(O.x)
                               + fmaxf(a4[hf * 2]     + bias_r[p][hn][0], 0.0f);
                    float x1 = __half2float(O.y)
                               + fmaxf(a4[hf * 2 + 1] + bias_r[p][hn][1], 0.0f);
                    __half2 Nh = __floats2half2_rn(x0, x1);
                    v[i] = *reinterpret_cast<uint32_t*>(&Nh);
                }
                STSM4(addr, v);
            }
        }
        __syncthreads();
    }
}

__global__ __launch_bounds__(NTH, 2)
void recur_kernel(const float* __restrict__ x_in, float* __restrict__ out) {
    extern __shared__ char smem[];
    uint32_t sb = smem_u32(smem);
    int n  = blockIdx.y;
    int m0 = blockIdx.x * MT;
    int t  = threadIdx.x;
    int l  = t & 31;
    int wid = t >> 5;
    int warp_m = wid >> 2;
    int warp_n = wid & 3;

    int nact = g_nact[n];
    ((float*)(smem + OFF_BS))[t] = g_bias[n * D_ + t];

    // ---- initial x load -> fp16 tile ----
    {
        int m = t >> 2, q = t & 3;
        const float4* src =
            (const float4*)(x_in + ((size_t)(m0 + m) * N_ + n) * D_) + q * 16;
        char* rowH = smem + OFF_XH + m * XSTR;
#pragma unroll
        for (int c = 0; c < 16; c++) {
            float4 v = src[c];
            int k = q * 64 + c * 4;
            __half2 h0 = __floats2half2_rn(v.x, v.y);
            __half2 h1 = __floats2half2_rn(v.z, v.w);
            *(uint32_t*)(rowH + k * 2)     = *reinterpret_cast<uint32_t*>(&h0);
            *(uint32_t*)(rowH + k * 2 + 4) = *reinterpret_cast<uint32_t*>(&h1);
        }
    }
    __syncthreads();

    const uint32_t aBaseH = sb + OFF_XH + (uint32_t)(warp_m * 32 + (l & 15)) * XSTR
                            + (uint32_t)(l >> 4) * 16;
    // epilogue LDSM/STSM lane address: matrix (l>>3): 0=(r0-7,c0-7) 1=(r8-15,c0-7)
    // 2=(r0-7,c8-15) 3=(r8-15,c8-15); lane supplies row (l&7) of its matrix.
    const uint32_t eBase = sb + OFF_XH
                           + (uint32_t)((l & 7) + ((l >> 3) & 1) * 8) * XSTR
                           + (uint32_t)((l >> 4) * 16);
    const uint4* gB = reinterpret_cast<const uint4*>(g_wB) + (size_t)n * 16 * 16 * 32;

    switch (nact) {
        case 128: run_main<128>(smem, gB, aBaseH, eBase, warp_m, warp_n, l); break;
        case 160: run_main<160>(smem, gB, aBaseH, eBase, warp_m, warp_n, l); break;
        case 192: run_main<192>(smem, gB, aBaseH, eBase, warp_m, warp_n, l); break;
        case 224: run_main<224>(smem, gB, aBaseH, eBase, warp_m, warp_n, l); break;
        default:  run_main<256>(smem, gB, aBaseH, eBase, warp_m, warp_n, l); break;
    }

    // ---- final store: fp16 -> fp32 ----
    {
        int m = t >> 2, q = t & 3;
        float4* dst = (float4*)(out + ((size_t)(m0 + m) * N_ + n) * D_) + q * 16;
        const char* rowH = smem + OFF_XH + m * XSTR;
#pragma unroll
        for (int c = 0; c < 16; c++) {
            int k = q * 64 + c * 4;
            uint32_t h0 = *(const uint32_t*)(rowH + k * 2);
            uint32_t h1 = *(const uint32_t*)(rowH + k * 2 + 4);
            __half2 H0 = *(__half2*)&h0, H1 = *(__half2*)&h1;
            float4 v;
            v.x = __half2float(H0.x);
            v.y = __half2float(H0.y);
            v.z = __half2float(H1.x);
            v.w = __half2float(H1.y);
            dst[c] = v;
        }
    }
}

// ---------------------------------------------------------------------------
extern "C" void kernel_launch(void* const* d_in, const int* in_sizes, int n_in,
                              void* d_out, int out_size) {
    const float* x  = (const float*)d_in[0];
    const float* w  = (const float*)d_in[1];
    const float* b  = (const float*)d_in[2];
    const float* wm = (const float*)d_in[3];
    const float* bm = (const float*)d_in[4];
    float* out = (float*)d_out;

    prep_kernel<<<dim3(N_, 16), 512>>>(w, wm, b, bm);

    cudaFuncSetAttribute(recur_kernel,
                         cudaFuncAttributeMaxDynamicSharedMemorySize, SMEM_SZ);
    recur_kernel<<<dim3(B_ / MT, N_), NTH, SMEM_SZ>>>(x, out);
}